// round 10
// baseline (speedup 1.0000x reference)
#include <cuda_runtime.h>
#include <cstdint>
#include <cstddef>

#define B_ 8192
#define N_ 512
#define NB 8            // batches per block
#define GRID (B_ / NB)  // 1024 persistent-ish blocks

// fp32 cyclic Jacobi rotation on symmetric 3x3 (branchy: skips converged)
#define JROT(app, aqq, apq, arp, arq, vAp, vAq, vBp, vBq, vCp, vCq) do {      \
    float _a = (apq);                                                          \
    if (fabsf(_a) > 1e-12f * (fabsf(app) + fabsf(aqq))) {                      \
        float _th = 0.5f * ((aqq) - (app)) / _a;                               \
        float _t = copysignf(1.f, _th) / (fabsf(_th) + sqrtf(fmaf(_th, _th, 1.f))); \
        float _c = rsqrtf(fmaf(_t, _t, 1.f));                                  \
        float _s = _t * _c;                                                    \
        (app) -= _t * _a; (aqq) += _t * _a; (apq) = 0.f;                       \
        float _rp = (arp), _rq = (arq);                                        \
        (arp) = _c * _rp - _s * _rq; (arq) = _s * _rp + _c * _rq;              \
        float _x;                                                              \
        _x = (vAp); (vAp) = _c * _x - _s * (vAq); (vAq) = _s * _x + _c * (vAq);\
        _x = (vBp); (vBp) = _c * _x - _s * (vBq); (vBq) = _s * _x + _c * (vBq);\
        _x = (vCp); (vCp) = _c * _x - _s * (vCq); (vCq) = _s * _x + _c * (vCq);\
    } } while (0)

__device__ __forceinline__ float frsqrt(float x) {
    float y = rsqrtf(x);
    return y * (1.5f - (0.5f * x) * y * y);
}

__device__ __forceinline__ void cp16(unsigned int dst, const void* src) {
    asm volatile("cp.async.cg.shared.global [%0], [%1], 16;" :: "r"(dst), "l"(src));
}
__device__ __forceinline__ void cp_commit() {
    asm volatile("cp.async.commit_group;");
}
__device__ __forceinline__ void cp_wait0() {
    asm volatile("cp.async.wait_group 0;");
}

// ---------------------------------------------------------------------------
// Fused + pipelined: each block handles NB consecutive batches. Batch i+1 is
// prefetched via cp.async into a single smem stage while batch i's SVD runs,
// keeping DRAM busy through the serial bubble. Thread t owns its own stage
// slots (prefetches and reads back only slot t) -> single buffer, no extra
// barriers needed beyond the two sred/srt barriers.
// ---------------------------------------------------------------------------
__global__ __launch_bounds__(128) void k_fused(
    const float* __restrict__ pred, const float* __restrict__ truc,
    const float* __restrict__ wgt, const unsigned int* __restrict__ msk,
    float* __restrict__ out)
{
    __shared__ float4 st_t[3][128];
    __shared__ float4 st_p[3][128];
    __shared__ float4 st_w[128];
    __shared__ uint4  st_m[128];
    __shared__ float  sred[4][16];
    __shared__ float  srt[12];

    int tid = threadIdx.x;
    int lane = tid & 31, wid = tid >> 5;
    int b0 = blockIdx.x * NB;

    unsigned int aT0 = (unsigned int)__cvta_generic_to_shared(&st_t[0][tid]);
    unsigned int aT1 = (unsigned int)__cvta_generic_to_shared(&st_t[1][tid]);
    unsigned int aT2 = (unsigned int)__cvta_generic_to_shared(&st_t[2][tid]);
    unsigned int aP0 = (unsigned int)__cvta_generic_to_shared(&st_p[0][tid]);
    unsigned int aP1 = (unsigned int)__cvta_generic_to_shared(&st_p[1][tid]);
    unsigned int aP2 = (unsigned int)__cvta_generic_to_shared(&st_p[2][tid]);
    unsigned int aW  = (unsigned int)__cvta_generic_to_shared(&st_w[tid]);
    unsigned int aM  = (unsigned int)__cvta_generic_to_shared(&st_m[tid]);

    // prologue: prefetch first batch
    {
        int b = b0;
        const float4* tg = reinterpret_cast<const float4*>(truc + (size_t)b * 1536) + tid * 3;
        const float4* pg = reinterpret_cast<const float4*>(pred + (size_t)b * 1536) + tid * 3;
        cp16(aT0, tg); cp16(aT1, tg + 1); cp16(aT2, tg + 2);
        cp16(aP0, pg); cp16(aP1, pg + 1); cp16(aP2, pg + 2);
        cp16(aW, wgt + (size_t)b * 512 + tid * 4);
        cp16(aM, msk + (size_t)b * 512 + tid * 4);
        cp_commit();
    }

    for (int i = 0; i < NB; i++) {
        int b = b0 + i;

        cp_wait0();
        float4 tv0 = st_t[0][tid], tv1 = st_t[1][tid], tv2 = st_t[2][tid];
        float4 pv0 = st_p[0][tid], pv1 = st_p[1][tid], pv2 = st_p[2][tid];
        float4 wv4 = st_w[tid];
        uint4  mv  = st_m[tid];

        float ta[12] = { tv0.x, tv0.y, tv0.z, tv0.w, tv1.x, tv1.y, tv1.z, tv1.w,
                         tv2.x, tv2.y, tv2.z, tv2.w };
        float pa[12] = { pv0.x, pv0.y, pv0.z, pv0.w, pv1.x, pv1.y, pv1.z, pv1.w,
                         pv2.x, pv2.y, pv2.z, pv2.w };
        float wa[4]  = { wv4.x, wv4.y, wv4.z, wv4.w };
        unsigned int ma[4] = { mv.x, mv.y, mv.z, mv.w };

        float acc[16];
#pragma unroll
        for (int k = 0; k < 16; k++) acc[k] = 0.f;
        unsigned int m4 = 0;

#pragma unroll
        for (int k = 0; k < 4; k++) {
            unsigned int on = (ma[k] != 0u);
            m4 |= on << k;
            float w = on ? wa[k] : 0.f;
            float tx = ta[3 * k], ty = ta[3 * k + 1], tz = ta[3 * k + 2];
            float px = pa[3 * k], py = pa[3 * k + 1], pz = pa[3 * k + 2];
            float wtx = w * tx, wty = w * ty, wtz = w * tz;
            acc[0] = fmaf(wtx, px, acc[0]); acc[1] = fmaf(wtx, py, acc[1]); acc[2] = fmaf(wtx, pz, acc[2]);
            acc[3] = fmaf(wty, px, acc[3]); acc[4] = fmaf(wty, py, acc[4]); acc[5] = fmaf(wty, pz, acc[5]);
            acc[6] = fmaf(wtz, px, acc[6]); acc[7] = fmaf(wtz, py, acc[7]); acc[8] = fmaf(wtz, pz, acc[8]);
            acc[9] += wtx; acc[10] += wty; acc[11] += wtz;
            acc[12] = fmaf(w, px, acc[12]); acc[13] = fmaf(w, py, acc[13]); acc[14] = fmaf(w, pz, acc[14]);
            acc[15] += w;
        }

        // register-halving butterfly: 16 accs -> 1 per lane in 16 shuffles.
        // After all levels, even lane 2m holds the full-warp sum of acc m.
#pragma unroll
        for (int k = 0; k < 8; k++) {
            bool hi = (lane & 16) != 0;
            float give = hi ? acc[k] : acc[k + 8];
            float keep = hi ? acc[k + 8] : acc[k];
            acc[k] = keep + __shfl_xor_sync(0xFFFFFFFFu, give, 16);
        }
#pragma unroll
        for (int k = 0; k < 4; k++) {
            bool hi = (lane & 8) != 0;
            float give = hi ? acc[k] : acc[k + 4];
            float keep = hi ? acc[k + 4] : acc[k];
            acc[k] = keep + __shfl_xor_sync(0xFFFFFFFFu, give, 8);
        }
#pragma unroll
        for (int k = 0; k < 2; k++) {
            bool hi = (lane & 4) != 0;
            float give = hi ? acc[k] : acc[k + 2];
            float keep = hi ? acc[k + 2] : acc[k];
            acc[k] = keep + __shfl_xor_sync(0xFFFFFFFFu, give, 4);
        }
        {
            bool hi = (lane & 2) != 0;
            float give = hi ? acc[0] : acc[1];
            float keep = hi ? acc[1] : acc[0];
            acc[0] = keep + __shfl_xor_sync(0xFFFFFFFFu, give, 2);
        }
        acc[0] += __shfl_xor_sync(0xFFFFFFFFu, acc[0], 1);

        if ((lane & 1) == 0)
            sred[wid][lane >> 1] = acc[0];
        __syncthreads();   // sred ready; all threads done reading their stage slots

        // prefetch next batch during the SVD bubble (own-slot discipline: safe)
        if (i + 1 < NB) {
            int bn = b + 1;
            const float4* tg = reinterpret_cast<const float4*>(truc + (size_t)bn * 1536) + tid * 3;
            const float4* pg = reinterpret_cast<const float4*>(pred + (size_t)bn * 1536) + tid * 3;
            cp16(aT0, tg); cp16(aT1, tg + 1); cp16(aT2, tg + 2);
            cp16(aP0, pg); cp16(aP1, pg + 1); cp16(aP2, pg + 2);
            cp16(aW, wgt + (size_t)bn * 512 + tid * 4);
            cp16(aM, msk + (size_t)bn * 512 + tid * 4);
            cp_commit();
        }

        if (tid == 0) {
            float r[16];
#pragma unroll
            for (int k = 0; k < 16; k++)
                r[k] = sred[0][k] + sred[1][k] + sred[2][k] + sred[3][k];

            float inv = 1.f / r[15];
            float c0 = r[9] * inv, c1 = r[10] * inv, c2 = r[11] * inv;

            float cov[9];
#pragma unroll
            for (int ii = 0; ii < 3; ii++)
#pragma unroll
                for (int j = 0; j < 3; j++)
                    cov[ii * 3 + j] = r[ii * 3 + j] - r[9 + ii] * r[12 + j] * inv;

            float m00 = 0, m01 = 0, m02 = 0, m11 = 0, m12 = 0, m22 = 0;
#pragma unroll
            for (int k = 0; k < 3; k++) {
                float a0 = cov[k * 3], a1 = cov[k * 3 + 1], a2 = cov[k * 3 + 2];
                m00 = fmaf(a0, a0, m00); m01 = fmaf(a0, a1, m01); m02 = fmaf(a0, a2, m02);
                m11 = fmaf(a1, a1, m11); m12 = fmaf(a1, a2, m12); m22 = fmaf(a2, a2, m22);
            }

            float v00 = 1, v01 = 0, v02 = 0, v10 = 0, v11 = 1, v12 = 0, v20 = 0, v21 = 0, v22 = 1;
#pragma unroll
            for (int sweep = 0; sweep < 5; sweep++) {
                JROT(m00, m11, m01, m02, m12, v00, v01, v10, v11, v20, v21);
                JROT(m00, m22, m02, m01, m12, v00, v02, v10, v12, v20, v22);
                JROT(m11, m22, m12, m01, m02, v01, v02, v11, v12, v21, v22);
            }

            int imin = 0; float lmin = m00;
            if (m11 < lmin) { lmin = m11; imin = 1; }
            if (m22 < lmin) { lmin = m22; imin = 2; }
            int ia = (imin == 0) ? 1 : 0;
            int ib = (imin == 2) ? 1 : 2;

            float vd[9] = { v00, v01, v02, v10, v11, v12, v20, v21, v22 };

            {
                float ax = vd[ia], ay = vd[3 + ia], az = vd[6 + ia];
                float bx = vd[ib], by = vd[3 + ib], bz = vd[6 + ib];
                float cx = ay * bz - az * by;
                float cy = az * bx - ax * bz;
                float cz = ax * by - ay * bx;
                float inm = frsqrt(cx * cx + cy * cy + cz * cz);
                vd[imin] = cx * inm; vd[3 + imin] = cy * inm; vd[6 + imin] = cz * inm;
            }

            double det = (double)cov[0] * ((double)cov[4] * cov[8] - (double)cov[5] * cov[7])
                       - (double)cov[1] * ((double)cov[3] * cov[8] - (double)cov[5] * cov[6])
                       + (double)cov[2] * ((double)cov[3] * cov[7] - (double)cov[4] * cov[6]);

            float rot[9] = { 0, 0, 0, 0, 0, 0, 0, 0, 0 };
#pragma unroll
            for (int ii = 0; ii < 3; ii++) {
                float vx = vd[ii], vy = vd[3 + ii], vz = vd[6 + ii];
                float g0 = cov[0] * vx + cov[1] * vy + cov[2] * vz;
                float g1 = cov[3] * vx + cov[4] * vy + cov[5] * vz;
                float g2 = cov[6] * vx + cov[7] * vy + cov[8] * vz;
                float coef = frsqrt(fmaf(g0, g0, fmaf(g1, g1, g2 * g2)));
                if (ii == imin && det < 0.0) coef = -coef;
                rot[0] = fmaf(coef * vx, g0, rot[0]); rot[1] = fmaf(coef * vx, g1, rot[1]); rot[2] = fmaf(coef * vx, g2, rot[2]);
                rot[3] = fmaf(coef * vy, g0, rot[3]); rot[4] = fmaf(coef * vy, g1, rot[4]); rot[5] = fmaf(coef * vy, g2, rot[5]);
                rot[6] = fmaf(coef * vz, g0, rot[6]); rot[7] = fmaf(coef * vz, g1, rot[7]); rot[8] = fmaf(coef * vz, g2, rot[8]);
            }

#pragma unroll
            for (int k = 0; k < 9; k++) srt[k] = rot[k];
            srt[9] = c0; srt[10] = c1; srt[11] = c2;
        }
        __syncthreads();

        float r00 = srt[0], r01 = srt[1], r02 = srt[2];
        float r10 = srt[3], r11 = srt[4], r12 = srt[5];
        float r20 = srt[6], r21 = srt[7], r22 = srt[8];
        float c0 = srt[9], c1 = srt[10], c2 = srt[11];

        float4 ov[3];
        float* oa = reinterpret_cast<float*>(ov);
#pragma unroll
        for (int k = 0; k < 4; k++) {
            float m = (m4 >> k) & 1u ? 1.f : 0.f;
            float x = ta[3 * k] * m - c0;
            float y = ta[3 * k + 1] * m - c1;
            float z = ta[3 * k + 2] * m - c2;
            oa[3 * k + 0] = fmaf(r00, x, fmaf(r01, y, fmaf(r02, z, c0)));
            oa[3 * k + 1] = fmaf(r10, x, fmaf(r11, y, fmaf(r12, z, c1)));
            oa[3 * k + 2] = fmaf(r20, x, fmaf(r21, y, fmaf(r22, z, c2)));
        }

        float4* op = reinterpret_cast<float4*>(out + (size_t)b * 1536) + tid * 3;
        op[0] = ov[0]; op[1] = ov[1]; op[2] = ov[2];
    }
}

// ---------------------------------------------------------------------------
extern "C" void kernel_launch(void* const* d_in, const int* in_sizes, int n_in,
                              void* d_out, int out_size)
{
    const float* pred = (const float*)d_in[0];
    const float* truc = (const float*)d_in[1];
    const float* wgt  = (const float*)d_in[2];
    const unsigned int* msk = (const unsigned int*)d_in[3];
    float* out = (float*)d_out;

    k_fused<<<GRID, 128>>>(pred, truc, wgt, msk, out);
}

// round 11
// speedup vs baseline: 1.2714x; 1.2714x over previous
#include <cuda_runtime.h>
#include <cstdint>
#include <cstddef>

#define B_ 8192
#define N_ 512

// fp32 cyclic Jacobi rotation on symmetric 3x3 (branchy: skips converged)
#define JROT(app, aqq, apq, arp, arq, vAp, vAq, vBp, vBq, vCp, vCq) do {      \
    float _a = (apq);                                                          \
    if (fabsf(_a) > 1e-12f * (fabsf(app) + fabsf(aqq))) {                      \
        float _th = 0.5f * ((aqq) - (app)) / _a;                               \
        float _t = copysignf(1.f, _th) / (fabsf(_th) + sqrtf(fmaf(_th, _th, 1.f))); \
        float _c = rsqrtf(fmaf(_t, _t, 1.f));                                  \
        float _s = _t * _c;                                                    \
        (app) -= _t * _a; (aqq) += _t * _a; (apq) = 0.f;                       \
        float _rp = (arp), _rq = (arq);                                        \
        (arp) = _c * _rp - _s * _rq; (arq) = _s * _rp + _c * _rq;              \
        float _x;                                                              \
        _x = (vAp); (vAp) = _c * _x - _s * (vAq); (vAq) = _s * _x + _c * (vAq);\
        _x = (vBp); (vBp) = _c * _x - _s * (vBq); (vBq) = _s * _x + _c * (vBq);\
        _x = (vCp); (vCp) = _c * _x - _s * (vCq); (vCq) = _s * _x + _c * (vCq);\
    } } while (0)

__device__ __forceinline__ float frsqrt(float x) {
    float y = rsqrtf(x);
    return y * (1.5f - (0.5f * x) * y * y);
}

// ---------------------------------------------------------------------------
// Fused: block = batch. Register-halving butterfly reduce (16 SHFL total),
// per-block SVD executed on lane 0 of warp (b & 3) so concurrent blocks'
// serial SVD chains spread across all 4 SMSPs instead of piling on SMSP 0.
// ---------------------------------------------------------------------------
__global__ __launch_bounds__(128) void k_fused(
    const float* __restrict__ pred, const float* __restrict__ truc,
    const float* __restrict__ wgt, const unsigned int* __restrict__ msk,
    float* __restrict__ out)
{
    int b = blockIdx.x, tid = threadIdx.x;

    const float4* tp = reinterpret_cast<const float4*>(truc + (size_t)b * 1536) + tid * 3;
    const float4* pp = reinterpret_cast<const float4*>(pred + (size_t)b * 1536) + tid * 3;

    float4 tv0 = tp[0], tv1 = tp[1], tv2 = tp[2];
    float4 pv0 = pp[0], pv1 = pp[1], pv2 = pp[2];
    float4 wv4 = reinterpret_cast<const float4*>(wgt + (size_t)b * 512)[tid];
    uint4  mv  = reinterpret_cast<const uint4*>(msk + (size_t)b * 512)[tid];

    float ta[12] = { tv0.x, tv0.y, tv0.z, tv0.w, tv1.x, tv1.y, tv1.z, tv1.w,
                     tv2.x, tv2.y, tv2.z, tv2.w };
    float pa[12] = { pv0.x, pv0.y, pv0.z, pv0.w, pv1.x, pv1.y, pv1.z, pv1.w,
                     pv2.x, pv2.y, pv2.z, pv2.w };
    float wa[4]  = { wv4.x, wv4.y, wv4.z, wv4.w };
    unsigned int ma[4] = { mv.x, mv.y, mv.z, mv.w };

    float acc[16];
#pragma unroll
    for (int k = 0; k < 16; k++) acc[k] = 0.f;
    unsigned int m4 = 0;

#pragma unroll
    for (int k = 0; k < 4; k++) {
        unsigned int on = (ma[k] != 0u);
        m4 |= on << k;
        float w = on ? wa[k] : 0.f;
        float tx = ta[3 * k], ty = ta[3 * k + 1], tz = ta[3 * k + 2];
        float px = pa[3 * k], py = pa[3 * k + 1], pz = pa[3 * k + 2];
        float wtx = w * tx, wty = w * ty, wtz = w * tz;
        acc[0] = fmaf(wtx, px, acc[0]); acc[1] = fmaf(wtx, py, acc[1]); acc[2] = fmaf(wtx, pz, acc[2]);
        acc[3] = fmaf(wty, px, acc[3]); acc[4] = fmaf(wty, py, acc[4]); acc[5] = fmaf(wty, pz, acc[5]);
        acc[6] = fmaf(wtz, px, acc[6]); acc[7] = fmaf(wtz, py, acc[7]); acc[8] = fmaf(wtz, pz, acc[8]);
        acc[9] += wtx; acc[10] += wty; acc[11] += wtz;
        acc[12] = fmaf(w, px, acc[12]); acc[13] = fmaf(w, py, acc[13]); acc[14] = fmaf(w, pz, acc[14]);
        acc[15] += w;
    }

    // register-halving butterfly: 16 accs -> 1 per lane in 16 shuffles.
    // After all levels, even lane 2m holds the full-warp sum of acc index m.
    int lane = tid & 31, wid = tid >> 5;
#pragma unroll
    for (int i = 0; i < 8; i++) {
        bool hi = (lane & 16) != 0;
        float give = hi ? acc[i] : acc[i + 8];
        float keep = hi ? acc[i + 8] : acc[i];
        acc[i] = keep + __shfl_xor_sync(0xFFFFFFFFu, give, 16);
    }
#pragma unroll
    for (int i = 0; i < 4; i++) {
        bool hi = (lane & 8) != 0;
        float give = hi ? acc[i] : acc[i + 4];
        float keep = hi ? acc[i + 4] : acc[i];
        acc[i] = keep + __shfl_xor_sync(0xFFFFFFFFu, give, 8);
    }
#pragma unroll
    for (int i = 0; i < 2; i++) {
        bool hi = (lane & 4) != 0;
        float give = hi ? acc[i] : acc[i + 2];
        float keep = hi ? acc[i + 2] : acc[i];
        acc[i] = keep + __shfl_xor_sync(0xFFFFFFFFu, give, 4);
    }
    {
        bool hi = (lane & 2) != 0;
        float give = hi ? acc[0] : acc[1];
        float keep = hi ? acc[1] : acc[0];
        acc[0] = keep + __shfl_xor_sync(0xFFFFFFFFu, give, 2);
    }
    acc[0] += __shfl_xor_sync(0xFFFFFFFFu, acc[0], 1);

    __shared__ float sred[4][16];
    __shared__ float srt[12];
    if ((lane & 1) == 0)
        sred[wid][lane >> 1] = acc[0];
    __syncthreads();

    // SVD thread: lane 0 of warp (b & 3) -> chains of concurrent blocks land
    // on different SMSPs (wid % 4 == SMSP id).
    if (tid == ((b & 3) << 5)) {
        float r[16];
#pragma unroll
        for (int k = 0; k < 16; k++)
            r[k] = sred[0][k] + sred[1][k] + sred[2][k] + sred[3][k];

        float inv = 1.f / r[15];
        float c0 = r[9] * inv, c1 = r[10] * inv, c2 = r[11] * inv;

        float cov[9];
#pragma unroll
        for (int i = 0; i < 3; i++)
#pragma unroll
            for (int j = 0; j < 3; j++)
                cov[i * 3 + j] = r[i * 3 + j] - r[9 + i] * r[12 + j] * inv;

        // M = cov^T cov (symmetric)
        float m00 = 0, m01 = 0, m02 = 0, m11 = 0, m12 = 0, m22 = 0;
#pragma unroll
        for (int k = 0; k < 3; k++) {
            float a0 = cov[k * 3], a1 = cov[k * 3 + 1], a2 = cov[k * 3 + 2];
            m00 = fmaf(a0, a0, m00); m01 = fmaf(a0, a1, m01); m02 = fmaf(a0, a2, m02);
            m11 = fmaf(a1, a1, m11); m12 = fmaf(a1, a2, m12); m22 = fmaf(a2, a2, m22);
        }

        float v00 = 1, v01 = 0, v02 = 0, v10 = 0, v11 = 1, v12 = 0, v20 = 0, v21 = 0, v22 = 1;
#pragma unroll
        for (int sweep = 0; sweep < 5; sweep++) {
            JROT(m00, m11, m01, m02, m12, v00, v01, v10, v11, v20, v21);
            JROT(m00, m22, m02, m01, m12, v00, v02, v10, v12, v20, v22);
            JROT(m11, m22, m12, m01, m02, v01, v02, v11, v12, v21, v22);
        }

        int imin = 0; float lmin = m00;
        if (m11 < lmin) { lmin = m11; imin = 1; }
        if (m22 < lmin) { lmin = m22; imin = 2; }
        int ia = (imin == 0) ? 1 : 0;
        int ib = (imin == 2) ? 1 : 2;

        float vd[9] = { v00, v01, v02, v10, v11, v12, v20, v21, v22 }; // col = eigvec

        // rebuild smallest-sigma direction as cross of the dominant two
        {
            float ax = vd[ia], ay = vd[3 + ia], az = vd[6 + ia];
            float bx = vd[ib], by = vd[3 + ib], bz = vd[6 + ib];
            float cx = ay * bz - az * by;
            float cy = az * bx - ax * bz;
            float cz = ax * by - ay * bx;
            float inm = frsqrt(cx * cx + cy * cy + cz * cz);
            vd[imin] = cx * inm; vd[3 + imin] = cy * inm; vd[6 + imin] = cz * inm;
        }

        // det sign (fp64, short chain)
        double det = (double)cov[0] * ((double)cov[4] * cov[8] - (double)cov[5] * cov[7])
                   - (double)cov[1] * ((double)cov[3] * cov[8] - (double)cov[5] * cov[6])
                   + (double)cov[2] * ((double)cov[3] * cov[7] - (double)cov[4] * cov[6]);

        float rot[9] = { 0, 0, 0, 0, 0, 0, 0, 0, 0 };
#pragma unroll
        for (int i = 0; i < 3; i++) {
            float vx = vd[i], vy = vd[3 + i], vz = vd[6 + i];
            float g0 = cov[0] * vx + cov[1] * vy + cov[2] * vz;
            float g1 = cov[3] * vx + cov[4] * vy + cov[5] * vz;
            float g2 = cov[6] * vx + cov[7] * vy + cov[8] * vz;
            float coef = frsqrt(fmaf(g0, g0, fmaf(g1, g1, g2 * g2)));
            if (i == imin && det < 0.0) coef = -coef;
            rot[0] = fmaf(coef * vx, g0, rot[0]); rot[1] = fmaf(coef * vx, g1, rot[1]); rot[2] = fmaf(coef * vx, g2, rot[2]);
            rot[3] = fmaf(coef * vy, g0, rot[3]); rot[4] = fmaf(coef * vy, g1, rot[4]); rot[5] = fmaf(coef * vy, g2, rot[5]);
            rot[6] = fmaf(coef * vz, g0, rot[6]); rot[7] = fmaf(coef * vz, g1, rot[7]); rot[8] = fmaf(coef * vz, g2, rot[8]);
        }

#pragma unroll
        for (int k = 0; k < 9; k++) srt[k] = rot[k];
        srt[9] = c0; srt[10] = c1; srt[11] = c2;
    }
    __syncthreads();

    float r00 = srt[0], r01 = srt[1], r02 = srt[2];
    float r10 = srt[3], r11 = srt[4], r12 = srt[5];
    float r20 = srt[6], r21 = srt[7], r22 = srt[8];
    float c0 = srt[9], c1 = srt[10], c2 = srt[11];

    float4 ov[3];
    float* oa = reinterpret_cast<float*>(ov);
#pragma unroll
    for (int k = 0; k < 4; k++) {
        float m = (m4 >> k) & 1u ? 1.f : 0.f;
        float x = ta[3 * k] * m - c0;
        float y = ta[3 * k + 1] * m - c1;
        float z = ta[3 * k + 2] * m - c2;
        oa[3 * k + 0] = fmaf(r00, x, fmaf(r01, y, fmaf(r02, z, c0)));
        oa[3 * k + 1] = fmaf(r10, x, fmaf(r11, y, fmaf(r12, z, c1)));
        oa[3 * k + 2] = fmaf(r20, x, fmaf(r21, y, fmaf(r22, z, c2)));
    }

    float4* op = reinterpret_cast<float4*>(out + (size_t)b * 1536) + tid * 3;
    op[0] = ov[0]; op[1] = ov[1]; op[2] = ov[2];
}

// ---------------------------------------------------------------------------
extern "C" void kernel_launch(void* const* d_in, const int* in_sizes, int n_in,
                              void* d_out, int out_size)
{
    const float* pred = (const float*)d_in[0];
    const float* truc = (const float*)d_in[1];
    const float* wgt  = (const float*)d_in[2];
    const unsigned int* msk = (const unsigned int*)d_in[3];
    float* out = (float*)d_out;

    k_fused<<<B_, 128>>>(pred, truc, wgt, msk, out);
}

// round 12
// speedup vs baseline: 1.4464x; 1.1377x over previous
#include <cuda_runtime.h>
#include <cstdint>
#include <cstddef>

#define B_ 8192
#define N_ 512

__device__ __forceinline__ float frsqrt(float x) {
    float y = rsqrtf(x);
    return y * (1.5f - (0.5f * x) * y * y);
}

// eigenvector of symmetric M for eigenvalue lam: cross products of rows of
// (M - lam I); pick the best-conditioned (largest-norm) cross. ILP-parallel.
__device__ __forceinline__ void eigvec3(
    float m00, float m01, float m02, float m11, float m12, float m22,
    float lam, float& vx, float& vy, float& vz)
{
    float a00 = m00 - lam, a11 = m11 - lam, a22 = m22 - lam;
    // rows: r0=(a00,m01,m02) r1=(m01,a11,m12) r2=(m02,m12,a22)
    float c0x = m01 * m12 - m02 * a11;   // r0 x r1
    float c0y = m02 * m01 - a00 * m12;
    float c0z = a00 * a11 - m01 * m01;
    float c1x = m01 * a22 - m02 * m12;   // r0 x r2
    float c1y = m02 * m02 - a00 * a22;
    float c1z = a00 * m12 - m01 * m02;
    float c2x = a11 * a22 - m12 * m12;   // r1 x r2
    float c2y = m12 * m02 - m01 * a22;
    float c2z = m01 * m12 - a11 * m02;
    float n0 = fmaf(c0x, c0x, fmaf(c0y, c0y, c0z * c0z));
    float n1 = fmaf(c1x, c1x, fmaf(c1y, c1y, c1z * c1z));
    float n2 = fmaf(c2x, c2x, fmaf(c2y, c2y, c2z * c2z));
    float bx = c0x, by = c0y, bz = c0z, bn = n0;
    if (n1 > bn) { bx = c1x; by = c1y; bz = c1z; bn = n1; }
    if (n2 > bn) { bx = c2x; by = c2y; bz = c2z; bn = n2; }
    float inm = rsqrtf(bn + 1e-38f);
    vx = bx * inm; vy = by * inm; vz = bz * inm;
}

// ---------------------------------------------------------------------------
// Fused: block = batch. Register-halving butterfly reduce (16 SHFL),
// thread0 closed-form 3x3 eigendecomposition (short chain), apply.
// ---------------------------------------------------------------------------
__global__ __launch_bounds__(128) void k_fused(
    const float* __restrict__ pred, const float* __restrict__ truc,
    const float* __restrict__ wgt, const unsigned int* __restrict__ msk,
    float* __restrict__ out)
{
    int b = blockIdx.x, tid = threadIdx.x;

    const float4* tp = reinterpret_cast<const float4*>(truc + (size_t)b * 1536) + tid * 3;
    const float4* pp = reinterpret_cast<const float4*>(pred + (size_t)b * 1536) + tid * 3;

    float4 tv0 = tp[0], tv1 = tp[1], tv2 = tp[2];
    float4 pv0 = pp[0], pv1 = pp[1], pv2 = pp[2];
    float4 wv4 = reinterpret_cast<const float4*>(wgt + (size_t)b * 512)[tid];
    uint4  mv  = reinterpret_cast<const uint4*>(msk + (size_t)b * 512)[tid];

    float ta[12] = { tv0.x, tv0.y, tv0.z, tv0.w, tv1.x, tv1.y, tv1.z, tv1.w,
                     tv2.x, tv2.y, tv2.z, tv2.w };
    float pa[12] = { pv0.x, pv0.y, pv0.z, pv0.w, pv1.x, pv1.y, pv1.z, pv1.w,
                     pv2.x, pv2.y, pv2.z, pv2.w };
    float wa[4]  = { wv4.x, wv4.y, wv4.z, wv4.w };
    unsigned int ma[4] = { mv.x, mv.y, mv.z, mv.w };

    float acc[16];
#pragma unroll
    for (int k = 0; k < 16; k++) acc[k] = 0.f;
    unsigned int m4 = 0;

#pragma unroll
    for (int k = 0; k < 4; k++) {
        unsigned int on = (ma[k] != 0u);
        m4 |= on << k;
        float w = on ? wa[k] : 0.f;
        float tx = ta[3 * k], ty = ta[3 * k + 1], tz = ta[3 * k + 2];
        float px = pa[3 * k], py = pa[3 * k + 1], pz = pa[3 * k + 2];
        float wtx = w * tx, wty = w * ty, wtz = w * tz;
        acc[0] = fmaf(wtx, px, acc[0]); acc[1] = fmaf(wtx, py, acc[1]); acc[2] = fmaf(wtx, pz, acc[2]);
        acc[3] = fmaf(wty, px, acc[3]); acc[4] = fmaf(wty, py, acc[4]); acc[5] = fmaf(wty, pz, acc[5]);
        acc[6] = fmaf(wtz, px, acc[6]); acc[7] = fmaf(wtz, py, acc[7]); acc[8] = fmaf(wtz, pz, acc[8]);
        acc[9] += wtx; acc[10] += wty; acc[11] += wtz;
        acc[12] = fmaf(w, px, acc[12]); acc[13] = fmaf(w, py, acc[13]); acc[14] = fmaf(w, pz, acc[14]);
        acc[15] += w;
    }

    // register-halving butterfly: 16 accs -> 1 per lane in 16 shuffles.
    int lane = tid & 31, wid = tid >> 5;
#pragma unroll
    for (int i = 0; i < 8; i++) {
        bool hi = (lane & 16) != 0;
        float give = hi ? acc[i] : acc[i + 8];
        float keep = hi ? acc[i + 8] : acc[i];
        acc[i] = keep + __shfl_xor_sync(0xFFFFFFFFu, give, 16);
    }
#pragma unroll
    for (int i = 0; i < 4; i++) {
        bool hi = (lane & 8) != 0;
        float give = hi ? acc[i] : acc[i + 4];
        float keep = hi ? acc[i + 4] : acc[i];
        acc[i] = keep + __shfl_xor_sync(0xFFFFFFFFu, give, 8);
    }
#pragma unroll
    for (int i = 0; i < 2; i++) {
        bool hi = (lane & 4) != 0;
        float give = hi ? acc[i] : acc[i + 2];
        float keep = hi ? acc[i + 2] : acc[i];
        acc[i] = keep + __shfl_xor_sync(0xFFFFFFFFu, give, 4);
    }
    {
        bool hi = (lane & 2) != 0;
        float give = hi ? acc[0] : acc[1];
        float keep = hi ? acc[1] : acc[0];
        acc[0] = keep + __shfl_xor_sync(0xFFFFFFFFu, give, 2);
    }
    acc[0] += __shfl_xor_sync(0xFFFFFFFFu, acc[0], 1);

    __shared__ float sred[4][16];
    __shared__ float srt[12];
    if ((lane & 1) == 0)
        sred[wid][lane >> 1] = acc[0];
    __syncthreads();

    if (tid == 0) {
        float r[16];
#pragma unroll
        for (int k = 0; k < 16; k++)
            r[k] = sred[0][k] + sred[1][k] + sred[2][k] + sred[3][k];

        float inv = __fdividef(1.f, r[15]);
        float c0 = r[9] * inv, c1 = r[10] * inv, c2 = r[11] * inv;

        float cov[9];
#pragma unroll
        for (int i = 0; i < 3; i++)
#pragma unroll
            for (int j = 0; j < 3; j++)
                cov[i * 3 + j] = r[i * 3 + j] - r[9 + i] * r[12 + j] * inv;

        // det sign (fp64, short chain; runs concurrently on the idle dp pipe)
        double det = (double)cov[0] * ((double)cov[4] * cov[8] - (double)cov[5] * cov[7])
                   - (double)cov[1] * ((double)cov[3] * cov[8] - (double)cov[5] * cov[6])
                   + (double)cov[2] * ((double)cov[3] * cov[7] - (double)cov[4] * cov[6]);

        // M = cov^T cov (symmetric, SPD; eigenvalues = sigma^2)
        float m00 = 0, m01 = 0, m02 = 0, m11 = 0, m12 = 0, m22 = 0;
#pragma unroll
        for (int k = 0; k < 3; k++) {
            float a0 = cov[k * 3], a1 = cov[k * 3 + 1], a2 = cov[k * 3 + 2];
            m00 = fmaf(a0, a0, m00); m01 = fmaf(a0, a1, m01); m02 = fmaf(a0, a2, m02);
            m11 = fmaf(a1, a1, m11); m12 = fmaf(a1, a2, m12); m22 = fmaf(a2, a2, m22);
        }

        // closed-form eigenvalues (Smith's trigonometric method)
        float q  = (m00 + m11 + m22) * (1.f / 3.f);
        float a00 = m00 - q, a11 = m11 - q, a22 = m22 - q;
        float p1 = fmaf(m01, m01, fmaf(m02, m02, m12 * m12));
        float p2 = fmaf(a00, a00, fmaf(a11, a11, a22 * a22)) + 2.f * p1;
        float p  = sqrtf(p2 * (1.f / 6.f)) + 1e-30f;
        float invp = __fdividef(1.f, p);
        float detA = a00 * (a11 * a22 - m12 * m12)
                   - m01 * (m01 * a22 - m12 * m02)
                   + m02 * (m01 * m12 - a11 * m02);
        float rr = 0.5f * detA * invp * invp * invp;
        rr = fminf(1.f, fmaxf(-1.f, rr));
        float phi = acosf(rr) * (1.f / 3.f);
        float lmax = q + 2.f * p * __cosf(phi);
        float lmin = q + 2.f * p * __cosf(phi + 2.0943951023931953f);
        float lmid = 3.f * q - lmax - lmin;

        // eigenvectors: v1 (lmax), v2 (lmid, orthogonalized vs v1), v3 = v1 x v2
        float v1x, v1y, v1z, w2x, w2y, w2z;
        eigvec3(m00, m01, m02, m11, m12, m22, lmax, v1x, v1y, v1z);
        eigvec3(m00, m01, m02, m11, m12, m22, lmid, w2x, w2y, w2z);
        float d12 = fmaf(w2x, v1x, fmaf(w2y, v1y, w2z * v1z));
        w2x -= d12 * v1x; w2y -= d12 * v1y; w2z -= d12 * v1z;
        float in2 = rsqrtf(fmaf(w2x, w2x, fmaf(w2y, w2y, w2z * w2z)) + 1e-38f);
        float v2x = w2x * in2, v2y = w2y * in2, v2z = w2z * in2;
        float v3x = v1y * v2z - v1z * v2y;
        float v3y = v1z * v2x - v1x * v2z;
        float v3z = v1x * v2y - v1y * v2x;

        // rot = sum_i d_i * v_i * (cov v_i / ||cov v_i||)^T ; flip on min sigma
        float vd[9] = { v1x, v2x, v3x, v1y, v2y, v3y, v1z, v2z, v3z };
        float rot[9] = { 0, 0, 0, 0, 0, 0, 0, 0, 0 };
#pragma unroll
        for (int i = 0; i < 3; i++) {
            float vx = vd[i], vy = vd[3 + i], vz = vd[6 + i];
            float g0 = cov[0] * vx + cov[1] * vy + cov[2] * vz;
            float g1 = cov[3] * vx + cov[4] * vy + cov[5] * vz;
            float g2 = cov[6] * vx + cov[7] * vy + cov[8] * vz;
            float coef = frsqrt(fmaf(g0, g0, fmaf(g1, g1, g2 * g2)));
            if (i == 2 && det < 0.0) coef = -coef;   // column 2 = smallest sigma
            rot[0] = fmaf(coef * vx, g0, rot[0]); rot[1] = fmaf(coef * vx, g1, rot[1]); rot[2] = fmaf(coef * vx, g2, rot[2]);
            rot[3] = fmaf(coef * vy, g0, rot[3]); rot[4] = fmaf(coef * vy, g1, rot[4]); rot[5] = fmaf(coef * vy, g2, rot[5]);
            rot[6] = fmaf(coef * vz, g0, rot[6]); rot[7] = fmaf(coef * vz, g1, rot[7]); rot[8] = fmaf(coef * vz, g2, rot[8]);
        }

#pragma unroll
        for (int k = 0; k < 9; k++) srt[k] = rot[k];
        srt[9] = c0; srt[10] = c1; srt[11] = c2;
    }
    __syncthreads();

    float r00 = srt[0], r01 = srt[1], r02 = srt[2];
    float r10 = srt[3], r11 = srt[4], r12 = srt[5];
    float r20 = srt[6], r21 = srt[7], r22 = srt[8];
    float c0 = srt[9], c1 = srt[10], c2 = srt[11];

    float4 ov[3];
    float* oa = reinterpret_cast<float*>(ov);
#pragma unroll
    for (int k = 0; k < 4; k++) {
        float m = (m4 >> k) & 1u ? 1.f : 0.f;
        float x = ta[3 * k] * m - c0;
        float y = ta[3 * k + 1] * m - c1;
        float z = ta[3 * k + 2] * m - c2;
        oa[3 * k + 0] = fmaf(r00, x, fmaf(r01, y, fmaf(r02, z, c0)));
        oa[3 * k + 1] = fmaf(r10, x, fmaf(r11, y, fmaf(r12, z, c1)));
        oa[3 * k + 2] = fmaf(r20, x, fmaf(r21, y, fmaf(r22, z, c2)));
    }

    float4* op = reinterpret_cast<float4*>(out + (size_t)b * 1536) + tid * 3;
    op[0] = ov[0]; op[1] = ov[1]; op[2] = ov[2];
}

// ---------------------------------------------------------------------------
extern "C" void kernel_launch(void* const* d_in, const int* in_sizes, int n_in,
                              void* d_out, int out_size)
{
    const float* pred = (const float*)d_in[0];
    const float* truc = (const float*)d_in[1];
    const float* wgt  = (const float*)d_in[2];
    const unsigned int* msk = (const unsigned int*)d_in[3];
    float* out = (float*)d_out;

    k_fused<<<B_, 128>>>(pred, truc, wgt, msk, out);
}

// round 14
// speedup vs baseline: 1.4880x; 1.0287x over previous
#include <cuda_runtime.h>
#include <cstdint>
#include <cstddef>

#define B_ 8192
#define N_ 512

__device__ __forceinline__ float frsqrt(float x) {
    float y = rsqrtf(x);
    return y * (1.5f - (0.5f * x) * y * y);
}

// eigenvector of symmetric M for eigenvalue lam: cross products of rows of
// (M - lam I); pick the best-conditioned (largest-norm) cross.
__device__ __forceinline__ void eigvec3(
    float m00, float m01, float m02, float m11, float m12, float m22,
    float lam, float& vx, float& vy, float& vz)
{
    float a00 = m00 - lam, a11 = m11 - lam, a22 = m22 - lam;
    float c0x = m01 * m12 - m02 * a11;   // r0 x r1
    float c0y = m02 * m01 - a00 * m12;
    float c0z = a00 * a11 - m01 * m01;
    float c1x = m01 * a22 - m02 * m12;   // r0 x r2
    float c1y = m02 * m02 - a00 * a22;
    float c1z = a00 * m12 - m01 * m02;
    float c2x = a11 * a22 - m12 * m12;   // r1 x r2
    float c2y = m12 * m02 - m01 * a22;
    float c2z = m01 * m12 - a11 * m02;
    float n0 = fmaf(c0x, c0x, fmaf(c0y, c0y, c0z * c0z));
    float n1 = fmaf(c1x, c1x, fmaf(c1y, c1y, c1z * c1z));
    float n2 = fmaf(c2x, c2x, fmaf(c2y, c2y, c2z * c2z));
    float bx = c0x, by = c0y, bz = c0z, bn = n0;
    if (n1 > bn) { bx = c1x; by = c1y; bz = c1z; bn = n1; }
    if (n2 > bn) { bx = c2x; by = c2y; bz = c2z; bn = n2; }
    float inm = rsqrtf(bn + 1e-38f);
    vx = bx * inm; vy = by * inm; vz = bz * inm;
}

// ---------------------------------------------------------------------------
// Fused: block = batch. Butterfly reduce (16 SHFL), warp-0-parallel
// closed-form 3x3 eigendecomposition (lane-selected eigvec + lane-parallel
// rot columns), apply.
// ---------------------------------------------------------------------------
__global__ __launch_bounds__(128, 8) void k_fused(
    const float* __restrict__ pred, const float* __restrict__ truc,
    const float* __restrict__ wgt, const unsigned int* __restrict__ msk,
    float* __restrict__ out)
{
    int b = blockIdx.x, tid = threadIdx.x;

    const float4* tp = reinterpret_cast<const float4*>(truc + (size_t)b * 1536) + tid * 3;
    const float4* pp = reinterpret_cast<const float4*>(pred + (size_t)b * 1536) + tid * 3;

    float4 tv0 = tp[0], tv1 = tp[1], tv2 = tp[2];
    float4 pv0 = pp[0], pv1 = pp[1], pv2 = pp[2];
    float4 wv4 = reinterpret_cast<const float4*>(wgt + (size_t)b * 512)[tid];
    uint4  mv  = reinterpret_cast<const uint4*>(msk + (size_t)b * 512)[tid];

    float ta[12] = { tv0.x, tv0.y, tv0.z, tv0.w, tv1.x, tv1.y, tv1.z, tv1.w,
                     tv2.x, tv2.y, tv2.z, tv2.w };
    float pa[12] = { pv0.x, pv0.y, pv0.z, pv0.w, pv1.x, pv1.y, pv1.z, pv1.w,
                     pv2.x, pv2.y, pv2.z, pv2.w };
    float wa[4]  = { wv4.x, wv4.y, wv4.z, wv4.w };
    unsigned int ma[4] = { mv.x, mv.y, mv.z, mv.w };

    float acc[16];
#pragma unroll
    for (int k = 0; k < 16; k++) acc[k] = 0.f;
    unsigned int m4 = 0;

#pragma unroll
    for (int k = 0; k < 4; k++) {
        unsigned int on = (ma[k] != 0u);
        m4 |= on << k;
        float w = on ? wa[k] : 0.f;
        float tx = ta[3 * k], ty = ta[3 * k + 1], tz = ta[3 * k + 2];
        float px = pa[3 * k], py = pa[3 * k + 1], pz = pa[3 * k + 2];
        float wtx = w * tx, wty = w * ty, wtz = w * tz;
        acc[0] = fmaf(wtx, px, acc[0]); acc[1] = fmaf(wtx, py, acc[1]); acc[2] = fmaf(wtx, pz, acc[2]);
        acc[3] = fmaf(wty, px, acc[3]); acc[4] = fmaf(wty, py, acc[4]); acc[5] = fmaf(wty, pz, acc[5]);
        acc[6] = fmaf(wtz, px, acc[6]); acc[7] = fmaf(wtz, py, acc[7]); acc[8] = fmaf(wtz, pz, acc[8]);
        acc[9] += wtx; acc[10] += wty; acc[11] += wtz;
        acc[12] = fmaf(w, px, acc[12]); acc[13] = fmaf(w, py, acc[13]); acc[14] = fmaf(w, pz, acc[14]);
        acc[15] += w;
    }

    // register-halving butterfly: 16 accs -> 1 per lane in 16 shuffles.
    int lane = tid & 31, wid = tid >> 5;
#pragma unroll
    for (int i = 0; i < 8; i++) {
        bool hi = (lane & 16) != 0;
        float give = hi ? acc[i] : acc[i + 8];
        float keep = hi ? acc[i + 8] : acc[i];
        acc[i] = keep + __shfl_xor_sync(0xFFFFFFFFu, give, 16);
    }
#pragma unroll
    for (int i = 0; i < 4; i++) {
        bool hi = (lane & 8) != 0;
        float give = hi ? acc[i] : acc[i + 4];
        float keep = hi ? acc[i + 4] : acc[i];
        acc[i] = keep + __shfl_xor_sync(0xFFFFFFFFu, give, 8);
    }
#pragma unroll
    for (int i = 0; i < 2; i++) {
        bool hi = (lane & 4) != 0;
        float give = hi ? acc[i] : acc[i + 2];
        float keep = hi ? acc[i + 2] : acc[i];
        acc[i] = keep + __shfl_xor_sync(0xFFFFFFFFu, give, 4);
    }
    {
        bool hi = (lane & 2) != 0;
        float give = hi ? acc[0] : acc[1];
        float keep = hi ? acc[1] : acc[0];
        acc[0] = keep + __shfl_xor_sync(0xFFFFFFFFu, give, 2);
    }
    acc[0] += __shfl_xor_sync(0xFFFFFFFFu, acc[0], 1);

    __shared__ float sred[4][16];
    __shared__ float srt[12];
    if ((lane & 1) == 0)
        sred[wid][lane >> 1] = acc[0];
    __syncthreads();

    if (wid == 0) {   // all 32 lanes cooperate (lockstep, cheap parts redundant)
        float r[16];
#pragma unroll
        for (int k = 0; k < 16; k++)
            r[k] = sred[0][k] + sred[1][k] + sred[2][k] + sred[3][k];   // smem broadcast

        float inv = __fdividef(1.f, r[15]);
        float c0 = r[9] * inv, c1 = r[10] * inv, c2 = r[11] * inv;

        float cov[9];
#pragma unroll
        for (int i = 0; i < 3; i++)
#pragma unroll
            for (int j = 0; j < 3; j++)
                cov[i * 3 + j] = r[i * 3 + j] - r[9 + i] * r[12 + j] * inv;

        // det sign (fp64, redundant across lanes; short side-chain)
        double det = (double)cov[0] * ((double)cov[4] * cov[8] - (double)cov[5] * cov[7])
                   - (double)cov[1] * ((double)cov[3] * cov[8] - (double)cov[5] * cov[6])
                   + (double)cov[2] * ((double)cov[3] * cov[7] - (double)cov[4] * cov[6]);

        // M = cov^T cov (SPD; eigenvalues = sigma^2)
        float m00 = 0, m01 = 0, m02 = 0, m11 = 0, m12 = 0, m22 = 0;
#pragma unroll
        for (int k = 0; k < 3; k++) {
            float a0 = cov[k * 3], a1 = cov[k * 3 + 1], a2 = cov[k * 3 + 2];
            m00 = fmaf(a0, a0, m00); m01 = fmaf(a0, a1, m01); m02 = fmaf(a0, a2, m02);
            m11 = fmaf(a1, a1, m11); m12 = fmaf(a1, a2, m12); m22 = fmaf(a2, a2, m22);
        }

        // closed-form eigenvalues (Smith's trigonometric method)
        float q  = (m00 + m11 + m22) * (1.f / 3.f);
        float a00 = m00 - q, a11 = m11 - q, a22 = m22 - q;
        float p1 = fmaf(m01, m01, fmaf(m02, m02, m12 * m12));
        float p2 = fmaf(a00, a00, fmaf(a11, a11, a22 * a22)) + 2.f * p1;
        float p  = sqrtf(p2 * (1.f / 6.f)) + 1e-30f;
        float invp = __fdividef(1.f, p);
        float detA = a00 * (a11 * a22 - m12 * m12)
                   - m01 * (m01 * a22 - m12 * m02)
                   + m02 * (m01 * m12 - a11 * m02);
        float rr = 0.5f * detA * invp * invp * invp;
        rr = fminf(1.f, fmaxf(-1.f, rr));
        float phi = acosf(rr) * (1.f / 3.f);
        float lmax = q + 2.f * p * __cosf(phi);
        float lmin = q + 2.f * p * __cosf(phi + 2.0943951023931953f);
        float lmid = 3.f * q - lmax - lmin;

        // ONE eigvec3 with lane-selected eigenvalue: lane 0 -> lmax, lane 1 -> lmid
        float lam = (lane & 1) ? lmid : lmax;
        float vx, vy, vz;
        eigvec3(m00, m01, m02, m11, m12, m22, lam, vx, vy, vz);
        float v1x = __shfl_sync(0xFFFFFFFFu, vx, 0);
        float v1y = __shfl_sync(0xFFFFFFFFu, vy, 0);
        float v1z = __shfl_sync(0xFFFFFFFFu, vz, 0);
        float w2x = __shfl_sync(0xFFFFFFFFu, vx, 1);
        float w2y = __shfl_sync(0xFFFFFFFFu, vy, 1);
        float w2z = __shfl_sync(0xFFFFFFFFu, vz, 1);

        // Gram-Schmidt v2 vs v1; v3 = v1 x v2  (redundant on all lanes)
        float d12 = fmaf(w2x, v1x, fmaf(w2y, v1y, w2z * v1z));
        w2x -= d12 * v1x; w2y -= d12 * v1y; w2z -= d12 * v1z;
        float in2 = rsqrtf(fmaf(w2x, w2x, fmaf(w2y, w2y, w2z * w2z)) + 1e-38f);
        float v2x = w2x * in2, v2y = w2y * in2, v2z = w2z * in2;
        float v3x = v1y * v2z - v1z * v2y;
        float v3y = v1z * v2x - v1x * v2z;
        float v3z = v1x * v2y - v1y * v2x;

        // lane-parallel rot columns: lane i (0..2) builds d_i * v_i * u_i^T
        float ux = (lane == 1) ? v2x : ((lane == 2) ? v3x : v1x);
        float uy = (lane == 1) ? v2y : ((lane == 2) ? v3y : v1y);
        float uz = (lane == 1) ? v2z : ((lane == 2) ? v3z : v1z);
        float g0 = cov[0] * ux + cov[1] * uy + cov[2] * uz;
        float g1 = cov[3] * ux + cov[4] * uy + cov[5] * uz;
        float g2 = cov[6] * ux + cov[7] * uy + cov[8] * uz;
        float coef = frsqrt(fmaf(g0, g0, fmaf(g1, g1, g2 * g2)));
        if (lane == 2 && det < 0.0) coef = -coef;   // flip smallest-sigma column

        float qr[9];
        qr[0] = coef * ux * g0; qr[1] = coef * ux * g1; qr[2] = coef * ux * g2;
        qr[3] = coef * uy * g0; qr[4] = coef * uy * g1; qr[5] = coef * uy * g2;
        qr[6] = coef * uz * g0; qr[7] = coef * uz * g1; qr[8] = coef * uz * g2;
        // sum lanes 0..2 onto lane 0 (reads original values, so order is safe)
#pragma unroll
        for (int j = 0; j < 9; j++) {
            float t1 = __shfl_down_sync(0xFFFFFFFFu, qr[j], 1);
            float t2 = __shfl_down_sync(0xFFFFFFFFu, qr[j], 2);
            qr[j] = qr[j] + t1 + t2;
        }

        if (lane == 0) {
#pragma unroll
            for (int j = 0; j < 9; j++) srt[j] = qr[j];
            srt[9] = c0; srt[10] = c1; srt[11] = c2;
        }
    }
    __syncthreads();

    float r00 = srt[0], r01 = srt[1], r02 = srt[2];
    float r10 = srt[3], r11 = srt[4], r12 = srt[5];
    float r20 = srt[6], r21 = srt[7], r22 = srt[8];
    float c0 = srt[9], c1 = srt[10], c2 = srt[11];

    float4 ov[3];
    float* oa = reinterpret_cast<float*>(ov);
#pragma unroll
    for (int k = 0; k < 4; k++) {
        float m = (m4 >> k) & 1u ? 1.f : 0.f;
        float x = ta[3 * k] * m - c0;
        float y = ta[3 * k + 1] * m - c1;
        float z = ta[3 * k + 2] * m - c2;
        oa[3 * k + 0] = fmaf(r00, x, fmaf(r01, y, fmaf(r02, z, c0)));
        oa[3 * k + 1] = fmaf(r10, x, fmaf(r11, y, fmaf(r12, z, c1)));
        oa[3 * k + 2] = fmaf(r20, x, fmaf(r21, y, fmaf(r22, z, c2)));
    }

    float4* op = reinterpret_cast<float4*>(out + (size_t)b * 1536) + tid * 3;
    op[0] = ov[0]; op[1] = ov[1]; op[2] = ov[2];
}

// ---------------------------------------------------------------------------
extern "C" void kernel_launch(void* const* d_in, const int* in_sizes, int n_in,
                              void* d_out, int out_size)
{
    const float* pred = (const float*)d_in[0];
    const float* truc = (const float*)d_in[1];
    const float* wgt  = (const float*)d_in[2];
    const unsigned int* msk = (const unsigned int*)d_in[3];
    float* out = (float*)d_out;

    k_fused<<<B_, 128>>>(pred, truc, wgt, msk, out);
}